// round 2
// baseline (speedup 1.0000x reference)
#include <cuda_runtime.h>
#include <stdint.h>

// Problem constants (from reference setup_inputs)
#define BSZ      32
#define XMAX     1024
#define VOCAB    1000
#define YMAX     128
#define LSTATES  257          // 2*YMAX + 1
#define LPAD     288          // padded row stride for arg storage (== NTHREADS)
#define NTHREADS 288
#define PF       8            // prefetch depth (register ring)
#define CHUNK    128          // backtrace chunk (rows of arg staged in smem)
#define LOGZERO  (-1e10f)

#define MASK_ELEMS ((size_t)BSZ * (YMAX + 1) * XMAX)   // 32*129*1024

// Back-pointer (argmax code 0/1/2) scratch: [BSZ][XMAX][LPAD] bytes = 9.4 MB
__device__ uint8_t g_arg[(size_t)BSZ * XMAX * LPAD];

__global__ __launch_bounds__(NTHREADS, 1)
void fanat_kernel(const float* __restrict__ ctc,       // [BSZ, XMAX, VOCAB]
                  const int*   __restrict__ src_size,  // [BSZ]
                  const int*   __restrict__ ys,        // [BSZ, YMAX]
                  const int*   __restrict__ ylens,     // [BSZ]
                  const int*   __restrict__ blank_p,   // [1] or nullptr
                  float*       __restrict__ out)
{
    __shared__ float   bufA[NTHREADS + 4];
    __shared__ float   bufB[NTHREADS + 4];
    __shared__ float   alphaAt[LSTATES];
    __shared__ short   path_sh[LSTATES];
    __shared__ uint8_t sh_arg[CHUNK][LPAD];
    __shared__ short   states_sh[XMAX];
    __shared__ short   incl_sh[XMAX];
    __shared__ int     part_sh[256];
    __shared__ int     start_sh;

    const int b   = blockIdx.x;
    const int tid = threadIdx.x;
    const int s   = tid;
    const bool active = (s < LSTATES);

    const int blank = blank_p ? blank_p[0] : 0;
    const int ss = src_size[b];
    const int pl = 2 * ylens[b] + 1;

    // path token for this state: even -> blank, odd -> ys[(s-1)/2]
    int tok = blank;
    if (active && (s & 1)) tok = ys[b * YMAX + (s >> 1)];
    // path[s-2]
    int tok2 = blank;
    if (active && s >= 2 && (s & 1)) tok2 = ys[b * YMAX + ((s - 2) >> 1)];
    const bool same    = active && (s >= 2) && (tok == tok2);
    const bool outside = !(active && s < pl);
    if (active) path_sh[s] = (short)tok;

    const float* rowptr = ctc + (size_t)b * XMAX * VOCAB + tok;
    uint8_t* argbase = g_arg + ((size_t)b * XMAX) * LPAD + s;

    // init alpha buffers
    for (int i = tid; i < NTHREADS + 4; i += NTHREADS) {
        bufA[i] = LOGZERO;
        bufB[i] = LOGZERO;
    }
    __syncthreads();
    if (tid == 0) bufA[2] = 0.0f;     // alpha0[0] = 0
    __syncthreads();

    // ---------------- Forward Viterbi (sequential over t) ----------------
    // Register ring of PF prefetched gathered log-probs; the batch of PF
    // independent LDGs issues back-to-back (MLP=PF) so DRAM latency (~577cyc)
    // is covered by ~PF*step_cost of work.
    float pre[PF];
#pragma unroll
    for (int i = 0; i < PF; i++) pre[i] = rowptr[(size_t)i * VOCAB];

    for (int t0 = 0; t0 < XMAX; t0 += PF) {
        float nxtpre[PF];
        const bool more = (t0 + PF < XMAX);
        if (more) {
#pragma unroll
            for (int i = 0; i < PF; i++)
                nxtpre[i] = rowptr[(size_t)(t0 + PF + i) * VOCAB];
        }
#pragma unroll
        for (int i = 0; i < PF; i++) {
            const int t = t0 + i;
            const float lp = pre[i];

            const float* cur = (t & 1) ? bufB : bufA;
            float*       nxt = (t & 1) ? bufA : bufB;

            const float m0 = cur[s + 2];
            const float m1 = cur[s + 1];
            const float m2 = same ? LOGZERO : cur[s];

            float best = m0; int arg = 0;
            if (m1 > best) { best = m1; arg = 1; }   // first-max tie-break (jnp.argmax)
            if (m2 > best) { best = m2; arg = 2; }

            const float anew = (outside ? LOGZERO : best) + lp;
            nxt[s + 2] = anew;
            argbase[(size_t)t * LPAD] = (uint8_t)arg;
            if (active && (t + 1 == ss)) alphaAt[s] = anew;  // alpha at t = src_size
            __syncthreads();
        }
        if (more) {
#pragma unroll
            for (int i = 0; i < PF; i++) pre[i] = nxtpre[i];
        }
    }

    // ---------------- score / start state ----------------
    if (tid == 0) {
        const float s1 = alphaAt[pl - 1];
        const float s2 = alphaAt[pl - 2];
        start_sh = (s1 > s2) ? (pl - 1) : (pl - 2);
        out[b] = fmaxf(s1, s2);                                   // score
        out[32 + MASK_ELEMS + b] = (float)(ylens[b] + 1);         // ylens + 1
    }
    __syncthreads();
    const int start_state = start_sh;

    // ---------------- Backtrace (chunked via shared memory) ----------------
    int carry0 = 0;                   // only tid 0's copy matters
    for (int ck = (XMAX / CHUNK) - 1; ck >= 0; --ck) {
        const int lo = ck * CHUNK;
        // stage arg rows (lo+1 .. lo+CHUNK), clamped at XMAX-1; column == tid
        const uint8_t* gsrc = g_arg + ((size_t)b * XMAX + lo + 1) * LPAD + tid;
#pragma unroll 4
        for (int r = 0; r < CHUNK; ++r) {
            const int grow = lo + 1 + r;
            sh_arg[r][tid] = (grow < XMAX) ? gsrc[(size_t)r * LPAD] : (uint8_t)0;
        }
        __syncthreads();
        if (tid == 0) {
            int carry = carry0;
            for (int t = lo + CHUNK - 1; t >= lo; --t) {
                int val;
                if (t == ss - 1)      val = start_state;
                else if (t >= ss)     val = 0;
                else                  val = carry - (int)sh_arg[t - lo][carry];
                states_sh[t] = (short)val;
                carry = val;
            }
            carry0 = carry;
        }
        __syncthreads();
    }

    // ---------------- collapse repeats + exclusive token count ----------------
    int loc[4];
    if (tid < 256) {
        const int t_base = tid * 4;
        short a_prev = (t_base == 0) ? (short)0 : path_sh[states_sh[t_base - 1]];
        int sum = 0;
#pragma unroll
        for (int k = 0; k < 4; ++k) {
            const int t = t_base + k;
            const short a = path_sh[states_sh[t]];
            const short anew = (t > 0 && a == a_prev) ? (short)0 : a;
            a_prev = a;
            sum += (anew != (short)blank) ? 1 : 0;
            loc[k] = sum;
        }
        part_sh[tid] = sum;
    }
    __syncthreads();
    // Hillis-Steele inclusive scan over the 256 partials
    for (int off = 1; off < 256; off <<= 1) {
        int v = 0;
        if (tid < 256) {
            v = part_sh[tid];
            if (tid >= off) v += part_sh[tid - off];
        }
        __syncthreads();
        if (tid < 256) part_sh[tid] = v;
        __syncthreads();
    }
    if (tid < 256) {
        const int t_base = tid * 4;
        const int offs = (tid == 0) ? 0 : part_sh[tid - 1];
#pragma unroll
        for (int k = 0; k < 4; ++k)
            incl_sh[t_base + k] = (short)(offs + loc[k]);
    }
    __syncthreads();

    // ---------------- trigger_mask write ----------------
    // csum[t] (exclusive count) = incl_sh[t-1], csum[0] = 0
    const size_t mbase = 32 + (size_t)b * (YMAX + 1) * XMAX;
    for (int idx = tid; idx < (YMAX + 1) * XMAX; idx += NTHREADS) {
        const int j = idx >> 10;           // XMAX = 1024
        const int t = idx & (XMAX - 1);
        const bool in = (t < ss);
        const int c = (t == 0) ? 0 : (int)incl_sh[t - 1];
        bool v;
        if (j < YMAX) v = in && (c == j);
        else          v = in && (c == YMAX || t == ss - 1);
        out[mbase + idx] = v ? 1.0f : 0.0f;
    }
}

extern "C" void kernel_launch(void* const* d_in, const int* in_sizes, int n_in,
                              void* d_out, int out_size)
{
    // metadata order: ctc_out(f32), src_mask(bool, unused), src_size(i32),
    //                 ys(i32), ylens(i32), blank(i32 scalar)
    const float* ctc      = (const float*)d_in[0];
    const int*   src_size = (const int*)d_in[2];
    const int*   ys       = (const int*)d_in[3];
    const int*   ylens    = (const int*)d_in[4];
    const int*   blank_p  = (n_in > 5) ? (const int*)d_in[5] : nullptr;

    fanat_kernel<<<BSZ, NTHREADS>>>(ctc, src_size, ys, ylens, blank_p, (float*)d_out);
}

// round 3
// speedup vs baseline: 1.3525x; 1.3525x over previous
#include <cuda_runtime.h>
#include <stdint.h>

// Problem constants (from reference setup_inputs)
#define BSZ      32
#define XMAX     1024
#define VOCAB    1000
#define YMAX     128
#define LSTATES  257                   // 2*YMAX + 1
#define LOGZERO  (-1e10f)
#define G        6                     // prefetch group depth (steps)

#define MASK_ELEMS ((size_t)BSZ * (YMAX + 1) * XMAX)   // 32*129*1024

// small cross-kernel scratch (static device globals: allocation-guard legal)
__device__ short g_csum[BSZ * XMAX];   // exclusive non-blank count per (b,t)
__device__ int   g_ssv[BSZ];           // src_size per batch

// dynamic smem: bp codes, [XMAX][32] uint32 (2-bit code per state, 9 per word)
extern __shared__ uint32_t bp_sm[];

__global__ __launch_bounds__(32, 1)
void fanat_forward(const float* __restrict__ ctc,       // [BSZ, XMAX, VOCAB]
                   const int*   __restrict__ src_size,  // [BSZ]
                   const int*   __restrict__ ys,        // [BSZ, YMAX]
                   const int*   __restrict__ ylens,     // [BSZ]
                   const int*   __restrict__ blank_p,   // [1] or nullptr
                   float*       __restrict__ out)
{
    __shared__ float alphaAt[LSTATES + 3];
    __shared__ short states_sh[XMAX];
    __shared__ int   start_sh;

    const int b    = blockIdx.x;
    const int lane = threadIdx.x;

    const int blank = blank_p ? blank_p[0] : 0;
    const int ss = src_size[b];
    const int yl = ylens[b];
    const int pl = 2 * yl + 1;

    // Lane owns states s = 8*lane + k, k=0..8 (k=8 duplicates lane+1's k=0;
    // harmless redundant compute, keeps all lanes uniform -> 1 shfl/step).
    // Odd states' tokens: s=8l+{1,3,5,7} -> ys[4l + j]
    int tokO[4];
#pragma unroll
    for (int j = 0; j < 4; j++) tokO[j] = ys[b * YMAX + 4 * lane + j];

    // same_tr for odd states (path[s]==path[s-2]); even states s>=2 are always
    // "same" (blank==blank) -> m2 = LOGZERO for every even state.
    const int prevLab = (lane > 0) ? ys[b * YMAX + 4 * lane - 1] : -1;
    bool sameO[4];
    sameO[0] = (lane == 0) ? true : (tokO[0] == prevLab);  // s-2 < 0 for lane0
    sameO[1] = (tokO[1] == tokO[0]);
    sameO[2] = (tokO[2] == tokO[1]);
    sameO[3] = (tokO[3] == tokO[2]);

    bool outF[9];
#pragma unroll
    for (int k = 0; k < 9; k++) outF[k] = (8 * lane + k) >= pl;

    const float* base = ctc + (size_t)b * XMAX * VOCAB;

    float a[9];
#pragma unroll
    for (int k = 0; k < 9; k++) a[k] = LOGZERO;
    if (lane == 0) a[0] = 0.0f;

    // one Viterbi step: lb = lp[blank], l1..l7 = lp at odd-state tokens
    auto step = [&](int t, float lb, float l1, float l3, float l5, float l7) {
        float h1 = __shfl_up_sync(0xffffffffu, a[7], 1);   // alpha[8l-1]
        if (lane == 0) h1 = LOGZERO;
        const float lpk[9] = {lb, l1, lb, l3, lb, l5, lb, l7, lb};
        float na[9];
        uint32_t w = 0u;
#pragma unroll
        for (int k = 0; k < 9; k++) {
            const float m0 = a[k];
            const float m1 = (k == 0) ? h1 : a[k - 1];
            float m2;
            if (k & 1) {
                const float mm = (k == 1) ? h1 : a[k - 2];   // alpha[s-2]
                m2 = sameO[k >> 1] ? LOGZERO : mm;
            } else {
                m2 = LOGZERO;                                // even: always same/invalid
            }
            float best = fmaxf(m0, m1);
            int   arg  = (m1 > m0) ? 1 : 0;      // first-max tie-break (jnp.argmax)
            if (m2 > best) { best = m2; arg = 2; }
            na[k] = (outF[k] ? LOGZERO : best) + lpk[k];
            w |= (uint32_t)arg << (2 * k);
        }
        bp_sm[t * 32 + lane] = w;
#pragma unroll
        for (int k = 0; k < 9; k++) a[k] = na[k];
    };

    // ---------------- Forward Viterbi, t in [0, ss) ----------------
    float pb[G], p1[G], p3[G], p5[G], p7[G];
#pragma unroll
    for (int i = 0; i < G; i++) {
        const float* r = base + (size_t)i * VOCAB;
        pb[i] = r[blank];   p1[i] = r[tokO[0]]; p3[i] = r[tokO[1]];
        p5[i] = r[tokO[2]]; p7[i] = r[tokO[3]];
    }

    int t0 = 0;
    for (; t0 + G <= ss; t0 += G) {
        float nb[G], n1[G], n3[G], n5[G], n7[G];
#pragma unroll
        for (int i = 0; i < G; i++) {
            int tp = t0 + G + i; if (tp > XMAX - 1) tp = XMAX - 1;
            const float* r = base + (size_t)tp * VOCAB;
            nb[i] = r[blank];   n1[i] = r[tokO[0]]; n3[i] = r[tokO[1]];
            n5[i] = r[tokO[2]]; n7[i] = r[tokO[3]];
        }
#pragma unroll
        for (int i = 0; i < G; i++) step(t0 + i, pb[i], p1[i], p3[i], p5[i], p7[i]);
#pragma unroll
        for (int i = 0; i < G; i++) {
            pb[i] = nb[i]; p1[i] = n1[i]; p3[i] = n3[i]; p5[i] = n5[i]; p7[i] = n7[i];
        }
    }
    {   // tail (< G steps), values already prefetched in pb/p*
        const int rem = ss - t0;
#pragma unroll
        for (int i = 0; i < G; i++)
            if (i < rem) step(t0 + i, pb[i], p1[i], p3[i], p5[i], p7[i]);
    }

    // ---------------- score / start state (alpha at t = ss is in regs) ----------------
#pragma unroll
    for (int k = 0; k < 9; k++) {
        const int s = 8 * lane + k;
        if (s < LSTATES) alphaAt[s] = a[k];   // k=8 duplicate writes same value
    }
    __syncwarp();
    if (lane == 0) {
        const float s1 = alphaAt[pl - 1];
        const float s2 = alphaAt[pl - 2];
        start_sh = (s1 > s2) ? (pl - 1) : (pl - 2);
        out[b] = fmaxf(s1, s2);                              // score
        out[32 + MASK_ELEMS + b] = (float)(yl + 1);          // ylens + 1
    }
    __syncwarp();

    // ---------------- backtrace ----------------
    for (int t = ss + lane; t < XMAX; t += 32) states_sh[t] = 0;
    if (lane == 0) {
        int carry = start_sh;
        states_sh[ss - 1] = (short)carry;
        for (int t = ss - 2; t >= 0; --t) {
            int lidx = carry >> 3; if (lidx > 31) lidx = 31;      // state 256 -> lane31,k=8
            const uint32_t word = bp_sm[(t + 1) * 32 + lidx];
            const int kk = carry - (lidx << 3);
            carry -= (int)((word >> (2 * kk)) & 3u);
            states_sh[t] = (short)carry;
        }
    }
    __syncwarp();

    // ---------------- collapse repeats + exclusive non-blank count ----------------
    const int base_t = lane * 32;
    int prevTok = 0;                                     // shift fills 0 at t=0
    if (base_t > 0) {
        const int sp = states_sh[base_t - 1];
        prevTok = (sp & 1) ? ys[b * YMAX + ((sp - 1) >> 1)] : blank;
    }
    int lane_sum = 0;
    {
        int pt = prevTok;
        for (int i = 0; i < 32; i++) {
            const int st = states_sh[base_t + i];
            const int tk = (st & 1) ? ys[b * YMAX + ((st - 1) >> 1)] : blank;
            const int col = (tk == pt) ? 0 : tk;
            lane_sum += (col != blank) ? 1 : 0;
            pt = tk;
        }
    }
    // warp exclusive scan of lane sums
    int offs = lane_sum;
#pragma unroll
    for (int d = 1; d < 32; d <<= 1) {
        const int v = __shfl_up_sync(0xffffffffu, offs, d);
        if (lane >= d) offs += v;
    }
    offs -= lane_sum;
    {
        int pt = prevTok, run = offs;
        for (int i = 0; i < 32; i++) {
            const int t = base_t + i;
            g_csum[b * XMAX + t] = (short)run;           // exclusive count at t
            const int st = states_sh[t];
            const int tk = (st & 1) ? ys[b * YMAX + ((st - 1) >> 1)] : blank;
            const int col = (tk == pt) ? 0 : tk;
            run += (col != blank) ? 1 : 0;
            pt = tk;
        }
    }
    if (lane == 0) g_ssv[b] = ss;
}

// ---------------- trigger_mask writer: full-grid streaming store ----------------
__global__ __launch_bounds__(256)
void fanat_mask(float* __restrict__ out)
{
    const size_t idx4 = (size_t)blockIdx.x * 256 + threadIdx.x;
    const size_t e = idx4 * 4;
    if (e >= MASK_ELEMS) return;
    const int per_b = (YMAX + 1) * XMAX;
    const int bb  = (int)(e / per_b);
    const int rem = (int)(e % per_b);
    const int j   = rem >> 10;               // XMAX = 1024
    const int t0  = rem & (XMAX - 1);

    const int ss = g_ssv[bb];
    const short4 cs = *(const short4*)(g_csum + bb * XMAX + t0);
    const int cv[4] = {cs.x, cs.y, cs.z, cs.w};

    float4 v;
    float* vv = &v.x;
#pragma unroll
    for (int u = 0; u < 4; u++) {
        const int t = t0 + u;
        const bool in = (t < ss);
        const int c = cv[u];
        bool r;
        if (j < YMAX) r = in && (c == j);
        else          r = in && (c == YMAX || t == ss - 1);
        vv[u] = r ? 1.0f : 0.0f;
    }
    *(float4*)(out + 32 + e) = v;
}

extern "C" void kernel_launch(void* const* d_in, const int* in_sizes, int n_in,
                              void* d_out, int out_size)
{
    // metadata order: ctc_out(f32), src_mask(bool, unused), src_size(i32),
    //                 ys(i32), ylens(i32), blank(i32 scalar)
    const float* ctc      = (const float*)d_in[0];
    const int*   src_size = (const int*)d_in[2];
    const int*   ys       = (const int*)d_in[3];
    const int*   ylens    = (const int*)d_in[4];
    const int*   blank_p  = (n_in > 5) ? (const int*)d_in[5] : nullptr;

    const int smem = XMAX * 32 * (int)sizeof(uint32_t);   // 128 KB bp codes
    cudaFuncSetAttribute(fanat_forward,
                         cudaFuncAttributeMaxDynamicSharedMemorySize, smem);
    fanat_forward<<<BSZ, 32, smem>>>(ctc, src_size, ys, ylens, blank_p, (float*)d_out);

    const int nthr = (int)((MASK_ELEMS / 4 + 255) / 256);
    fanat_mask<<<nthr, 256>>>((float*)d_out);
}

// round 5
// speedup vs baseline: 1.4946x; 1.1051x over previous
#include <cuda_runtime.h>
#include <stdint.h>

// Problem constants (from reference setup_inputs)
#define BSZ      32
#define XMAX     1024
#define VOCAB    1000
#define YMAX     128
#define LSTATES  257                   // 2*YMAX + 1
#define LOGZERO  (-1e10f)
#define G        8                     // prefetch group depth (steps)
#define GROW     132                   // gathered row stride (floats): 128 tok + blank + pad

#define MASK_ELEMS ((size_t)BSZ * (YMAX + 1) * XMAX)   // 32*129*1024

// cross-kernel scratch (static device globals: allocation-guard legal)
__device__ __align__(16) float g_gather[(size_t)BSZ * XMAX * GROW];  // ~17 MB
__device__ __align__(16) short g_csum[BSZ * XMAX];  // exclusive non-blank count per (b,t)
__device__ int   g_ssv[BSZ];           // src_size per batch

// dynamic smem: bp codes, [XMAX][32] uint32 (2-bit code per state, 9 per word)
extern __shared__ uint32_t bp_sm[];

// ---------------- Stage 1: time-invariant column gather ----------------
// g_gather[b][t][j] = ctc[b][t][ys[b][j]] for j<128 ; [128] = ctc[b][t][blank]
__global__ __launch_bounds__(256)
void fanat_gather(const float* __restrict__ ctc,
                  const int*   __restrict__ ys,
                  const int*   __restrict__ blank_p)
{
    const int idx = blockIdx.x * 256 + threadIdx.x;
    const int total = BSZ * XMAX * GROW;
    if (idx >= total) return;
    const int j  = idx % GROW;
    if (j > 128) return;
    const int bt = idx / GROW;              // b*XMAX + t
    const int b  = bt >> 10;                // XMAX = 1024

    const int blank = blank_p ? blank_p[0] : 0;
    const int tok = (j < 128) ? ys[b * YMAX + j] : blank;
    g_gather[(size_t)bt * GROW + j] = ctc[(size_t)bt * VOCAB + tok];
}

// ---------------- Stage 2: single-warp-per-batch Viterbi ----------------
__global__ __launch_bounds__(32, 1)
void fanat_forward(const int*   __restrict__ src_size,  // [BSZ]
                   const int*   __restrict__ ys,        // [BSZ, YMAX]
                   const int*   __restrict__ ylens,     // [BSZ]
                   const int*   __restrict__ blank_p,   // [1] or nullptr
                   float*       __restrict__ out)
{
    __shared__ float alphaAt[LSTATES + 3];
    __shared__ short states_sh[XMAX];
    __shared__ int   start_sh;

    const int b    = blockIdx.x;
    const int lane = threadIdx.x;

    const int blank = blank_p ? blank_p[0] : 0;
    const int ss = src_size[b];
    const int yl = ylens[b];
    const int pl = 2 * yl + 1;

    // Lane owns states s = 8*lane + k, k=0..8 (k=8 duplicates lane+1's k=0;
    // redundant compute keeps lanes uniform -> 1 shfl/step, no barriers).
    int tokO[4];
#pragma unroll
    for (int j = 0; j < 4; j++) tokO[j] = ys[b * YMAX + 4 * lane + j];

    const int prevLab = (lane > 0) ? ys[b * YMAX + 4 * lane - 1] : -1;
    bool sameO[4];
    sameO[0] = (lane == 0) ? true : (tokO[0] == prevLab);  // s-2 < 0 for lane0
    sameO[1] = (tokO[1] == tokO[0]);
    sameO[2] = (tokO[2] == tokO[1]);
    sameO[3] = (tokO[3] == tokO[2]);

    bool outF[9];
#pragma unroll
    for (int k = 0; k < 9; k++) outF[k] = (8 * lane + k) >= pl;

    const float* grow_base = g_gather + (size_t)b * XMAX * GROW;

    float a[9];
#pragma unroll
    for (int k = 0; k < 9; k++) a[k] = LOGZERO;
    if (lane == 0) a[0] = 0.0f;

    auto step = [&](int t, float lb, float l1, float l3, float l5, float l7) {
        float h1 = __shfl_up_sync(0xffffffffu, a[7], 1);   // alpha[8l-1]
        if (lane == 0) h1 = LOGZERO;
        const float lpk[9] = {lb, l1, lb, l3, lb, l5, lb, l7, lb};
        float na[9];
        uint32_t w = 0u;
#pragma unroll
        for (int k = 0; k < 9; k++) {
            const float m0 = a[k];
            const float m1 = (k == 0) ? h1 : a[k - 1];
            float m2;
            if (k & 1) {
                const float mm = (k == 1) ? h1 : a[k - 2];   // alpha[s-2]
                m2 = sameO[k >> 1] ? LOGZERO : mm;
            } else {
                m2 = LOGZERO;                                // even: always "same"
            }
            float best = fmaxf(m0, m1);
            int   arg  = (m1 > m0) ? 1 : 0;      // first-max tie-break (jnp.argmax)
            if (m2 > best) { best = m2; arg = 2; }
            na[k] = (outF[k] ? LOGZERO : best) + lpk[k];
            w |= (uint32_t)arg << (2 * k);
        }
        bp_sm[t * 32 + lane] = w;
#pragma unroll
        for (int k = 0; k < 9; k++) a[k] = na[k];
    };

    // Forward Viterbi, t in [0, ss) — double-buffered prefetch of compact rows
    float4 pv[G];  float pb[G];
#pragma unroll
    for (int i = 0; i < G; i++) {
        const float* r = grow_base + (size_t)i * GROW;
        pv[i] = ((const float4*)r)[lane];
        pb[i] = r[128];
    }

    int t0 = 0;
    for (; t0 + G <= ss; t0 += G) {
        float4 nv[G];  float nb[G];
#pragma unroll
        for (int i = 0; i < G; i++) {
            int tp = t0 + G + i; if (tp > XMAX - 1) tp = XMAX - 1;
            const float* r = grow_base + (size_t)tp * GROW;
            nv[i] = ((const float4*)r)[lane];
            nb[i] = r[128];
        }
#pragma unroll
        for (int i = 0; i < G; i++)
            step(t0 + i, pb[i], pv[i].x, pv[i].y, pv[i].z, pv[i].w);
#pragma unroll
        for (int i = 0; i < G; i++) { pv[i] = nv[i]; pb[i] = nb[i]; }
    }
    {   // tail (< G steps), already prefetched
        const int rem = ss - t0;
#pragma unroll
        for (int i = 0; i < G; i++)
            if (i < rem) step(t0 + i, pb[i], pv[i].x, pv[i].y, pv[i].z, pv[i].w);
    }

    // ---------------- score / start state (alpha at t = ss is in regs) ----------------
#pragma unroll
    for (int k = 0; k < 9; k++) {
        const int s = 8 * lane + k;
        if (s < LSTATES) alphaAt[s] = a[k];
    }
    __syncwarp();
    if (lane == 0) {
        const float s1 = alphaAt[pl - 1];
        const float s2 = alphaAt[pl - 2];
        start_sh = (s1 > s2) ? (pl - 1) : (pl - 2);
        out[b] = fmaxf(s1, s2);                              // score
        out[32 + MASK_ELEMS + b] = (float)(yl + 1);          // ylens + 1
    }
    __syncwarp();

    // ---------------- backtrace (lane 0, LDS chase) ----------------
    for (int t = ss + lane; t < XMAX; t += 32) states_sh[t] = 0;
    if (lane == 0) {
        int carry = start_sh;
        states_sh[ss - 1] = (short)carry;
        for (int t = ss - 2; t >= 0; --t) {
            int lidx = carry >> 3; if (lidx > 31) lidx = 31;   // state 256 -> lane31,k=8
            const uint32_t word = bp_sm[(t + 1) * 32 + lidx];
            const int kk = carry - (lidx << 3);
            carry -= (int)((word >> (2 * kk)) & 3u);
            states_sh[t] = (short)carry;
        }
    }
    __syncwarp();

    // ---------------- collapse repeats + exclusive non-blank count ----------------
    const int base_t = lane * 32;
    int prevTok = 0;
    if (base_t > 0) {
        const int sp = states_sh[base_t - 1];
        prevTok = (sp & 1) ? ys[b * YMAX + ((sp - 1) >> 1)] : blank;
    }
    int lane_sum = 0;
    {
        int pt = prevTok;
        for (int i = 0; i < 32; i++) {
            const int st = states_sh[base_t + i];
            const int tk = (st & 1) ? ys[b * YMAX + ((st - 1) >> 1)] : blank;
            const int col = (tk == pt) ? 0 : tk;
            lane_sum += (col != blank) ? 1 : 0;
            pt = tk;
        }
    }
    int offs = lane_sum;
#pragma unroll
    for (int d = 1; d < 32; d <<= 1) {
        const int v = __shfl_up_sync(0xffffffffu, offs, d);
        if (lane >= d) offs += v;
    }
    offs -= lane_sum;
    {
        int pt = prevTok, run = offs;
        for (int i = 0; i < 32; i++) {
            const int t = base_t + i;
            g_csum[b * XMAX + t] = (short)run;               // exclusive count at t
            const int st = states_sh[t];
            const int tk = (st & 1) ? ys[b * YMAX + ((st - 1) >> 1)] : blank;
            const int col = (tk == pt) ? 0 : tk;
            run += (col != blank) ? 1 : 0;
            pt = tk;
        }
    }
    if (lane == 0) g_ssv[b] = ss;
}

// ---------------- Stage 3: trigger_mask streaming store ----------------
__global__ __launch_bounds__(256)
void fanat_mask(float* __restrict__ out)
{
    const size_t idx4 = (size_t)blockIdx.x * 256 + threadIdx.x;
    const size_t e = idx4 * 4;
    if (e >= MASK_ELEMS) return;
    const int per_b = (YMAX + 1) * XMAX;
    const int bb  = (int)(e / per_b);
    const int rem = (int)(e % per_b);
    const int j   = rem >> 10;               // XMAX = 1024
    const int t0  = rem & (XMAX - 1);

    const int ss = g_ssv[bb];
    const short4 cs = *(const short4*)(g_csum + bb * XMAX + t0);
    const int cv[4] = {cs.x, cs.y, cs.z, cs.w};

    float4 v;
    float* vv = &v.x;
#pragma unroll
    for (int u = 0; u < 4; u++) {
        const int t = t0 + u;
        const bool in = (t < ss);
        const int c = cv[u];
        bool r;
        if (j < YMAX) r = in && (c == j);
        else          r = in && (c == YMAX || t == ss - 1);
        vv[u] = r ? 1.0f : 0.0f;
    }
    *(float4*)(out + 32 + e) = v;
}

extern "C" void kernel_launch(void* const* d_in, const int* in_sizes, int n_in,
                              void* d_out, int out_size)
{
    // metadata order: ctc_out(f32), src_mask(bool, unused), src_size(i32),
    //                 ys(i32), ylens(i32), blank(i32 scalar)
    const float* ctc      = (const float*)d_in[0];
    const int*   src_size = (const int*)d_in[2];
    const int*   ys       = (const int*)d_in[3];
    const int*   ylens    = (const int*)d_in[4];
    const int*   blank_p  = (n_in > 5) ? (const int*)d_in[5] : nullptr;

    {   // Stage 1: gather
        const int total = BSZ * XMAX * GROW;
        fanat_gather<<<(total + 255) / 256, 256>>>(ctc, ys, blank_p);
    }

    {   // Stage 2: forward Viterbi + backtrace + csum
        const int smem = XMAX * 32 * (int)sizeof(uint32_t);   // 128 KB bp codes
        cudaFuncSetAttribute(fanat_forward,
                             cudaFuncAttributeMaxDynamicSharedMemorySize, smem);
        fanat_forward<<<BSZ, 32, smem>>>(src_size, ys, ylens, blank_p, (float*)d_out);
    }

    {   // Stage 3: trigger_mask
        const int nthr = (int)((MASK_ELEMS / 4 + 255) / 256);
        fanat_mask<<<nthr, 256>>>((float*)d_out);
    }
}

// round 7
// speedup vs baseline: 1.9714x; 1.3190x over previous
#include <cuda_runtime.h>
#include <stdint.h>

// Problem constants (from reference setup_inputs)
#define BSZ      32
#define XMAX     1024
#define VOCAB    1000
#define YMAX     128
#define LSTATES  257                   // 2*YMAX + 1
#define LOGZERO  (-1e10f)
#define GROW     132                   // gathered row stride (floats): 128 tok + blank + pad
#define RING     16                    // cp.async smem ring depth (rows)
#define ROWB     (GROW * 4)            // row bytes = 528

#define MASK_ELEMS ((size_t)BSZ * (YMAX + 1) * XMAX)   // 32*129*1024

// cross-kernel scratch (static device globals: allocation-guard legal)
__device__ __align__(16) float g_gather[(size_t)BSZ * XMAX * GROW];  // ~17 MB
__device__ __align__(16) short g_csum[BSZ * XMAX];  // exclusive non-blank count per (b,t)
__device__ int   g_ssv[BSZ];           // src_size per batch

// dynamic smem: [0,128KB) bp codes  |  [128KB, +RING*528B) gathered-row ring
extern __shared__ uint32_t dyn_sm[];

__device__ __forceinline__ uint32_t smem_u32(const void* p) {
    uint32_t a;
    asm("{ .reg .u64 t; cvta.to.shared.u64 t, %1; cvt.u32.u64 %0, t; }"
        : "=r"(a) : "l"(p));
    return a;
}
__device__ __forceinline__ void cp_async16(uint32_t dst, const void* src) {
    asm volatile("cp.async.cg.shared.global [%0], [%1], 16;" :: "r"(dst), "l"(src));
}
#define CP_COMMIT() asm volatile("cp.async.commit_group;" ::: "memory")
#define CP_WAIT14() asm volatile("cp.async.wait_group 14;" ::: "memory")

// ---------------- Stage 1: time-invariant column gather ----------------
// g_gather[b][t][j] = ctc[b][t][ys[b][j]] for j<128 ; [128] = ctc[b][t][blank]
__global__ __launch_bounds__(256)
void fanat_gather(const float* __restrict__ ctc,
                  const int*   __restrict__ ys,
                  const int*   __restrict__ blank_p)
{
    const int idx = blockIdx.x * 256 + threadIdx.x;
    const int total = BSZ * XMAX * GROW;
    if (idx >= total) return;
    const int j  = idx % GROW;
    if (j > 128) return;
    const int bt = idx / GROW;              // b*XMAX + t
    const int b  = bt >> 10;                // XMAX = 1024

    const int blank = blank_p ? blank_p[0] : 0;
    const int tok = (j < 128) ? ys[b * YMAX + j] : blank;
    g_gather[(size_t)bt * GROW + j] = ctc[(size_t)bt * VOCAB + tok];
}

// ---------------- Stage 2: single-warp-per-batch Viterbi ----------------
__global__ __launch_bounds__(32, 1)
void fanat_forward(const int*   __restrict__ src_size,  // [BSZ]
                   const int*   __restrict__ ys,        // [BSZ, YMAX]
                   const int*   __restrict__ ylens,     // [BSZ]
                   const int*   __restrict__ blank_p,   // [1] or nullptr
                   float*       __restrict__ out)
{
    __shared__ float alphaAt[LSTATES + 3];
    __shared__ short states_sh[XMAX];
    __shared__ int   start_sh;

    uint32_t* bp_sm = dyn_sm;                                  // [XMAX][32] u32
    char*     ring  = (char*)(dyn_sm + XMAX * 32);             // RING rows of 528B
    const uint32_t ring_s = smem_u32(ring);

    const int b    = blockIdx.x;
    const int lane = threadIdx.x;

    const int blank = blank_p ? blank_p[0] : 0;
    const int ss = src_size[b];
    const int yl = ylens[b];
    const int pl = 2 * yl + 1;

    // Lane owns states s = 8*lane + k, k=0..8 (k=8 duplicates lane+1's k=0;
    // redundant compute keeps lanes uniform -> 1 shfl/step, no barriers).
    int tokO[4];
#pragma unroll
    for (int j = 0; j < 4; j++) tokO[j] = ys[b * YMAX + 4 * lane + j];

    const int prevLab = (lane > 0) ? ys[b * YMAX + 4 * lane - 1] : -1;
    bool sameO[4];
    sameO[0] = (lane == 0) ? true : (tokO[0] == prevLab);  // s-2 < 0 for lane0
    sameO[1] = (tokO[1] == tokO[0]);
    sameO[2] = (tokO[2] == tokO[1]);
    sameO[3] = (tokO[3] == tokO[2]);

    bool outF[9];
#pragma unroll
    for (int k = 0; k < 9; k++) outF[k] = (8 * lane + k) >= pl;

    const float* grow_base = g_gather + (size_t)b * XMAX * GROW;

    // issue async copy of one gathered row into ring slot (row clamped)
    auto issue_row = [&](int row) {
        int rp = row; if (rp > XMAX - 1) rp = XMAX - 1;
        const char* src = (const char*)(grow_base + (size_t)rp * GROW);
        const uint32_t dst = ring_s + (row & (RING - 1)) * ROWB;
        cp_async16(dst + lane * 16, src + lane * 16);
        if (lane == 0) cp_async16(dst + 512, src + 512);   // floats 128..131 (blank)
        CP_COMMIT();
    };

    float a[9];
#pragma unroll
    for (int k = 0; k < 9; k++) a[k] = LOGZERO;
    if (lane == 0) a[0] = 0.0f;

    auto step = [&](int t, float lb, float l1, float l3, float l5, float l7) {
        float h1 = __shfl_up_sync(0xffffffffu, a[7], 1);   // alpha[8l-1]
        if (lane == 0) h1 = LOGZERO;
        const float lpk[9] = {lb, l1, lb, l3, lb, l5, lb, l7, lb};
        float na[9];
        uint32_t av[9];
#pragma unroll
        for (int k = 0; k < 9; k++) {
            const float m0 = a[k];
            const float m1 = (k == 0) ? h1 : a[k - 1];
            float m2;
            if (k & 1) {
                const float mm = (k == 1) ? h1 : a[k - 2];   // alpha[s-2]
                m2 = sameO[k >> 1] ? LOGZERO : mm;
            } else {
                m2 = LOGZERO;                                // even: always "same"
            }
            float best = fmaxf(m0, m1);
            int   arg  = (m1 > m0) ? 1 : 0;      // first-max tie-break (jnp.argmax)
            if (m2 > best) { best = m2; arg = 2; }
            na[k] = (outF[k] ? LOGZERO : best) + lpk[k];
            av[k] = (uint32_t)arg << (2 * k);
        }
        // balanced OR tree (avoid 9-deep serial chain)
        const uint32_t w01 = av[0] | av[1], w23 = av[2] | av[3];
        const uint32_t w45 = av[4] | av[5], w67 = av[6] | av[7];
        const uint32_t w = (w01 | w23) | (w45 | w67) | av[8];
        bp_sm[t * 32 + lane] = w;
#pragma unroll
        for (int k = 0; k < 9; k++) a[k] = na[k];
    };

    // ---- pipeline prologue: fill the ring, load row 0 into regs ----
#pragma unroll
    for (int r = 0; r < RING; r++) issue_row(r);
    CP_WAIT14();                                  // rows 0..1 resident
    const float4* ring4 = (const float4*)ring;
    const float*  ringf = (const float*)ring;
    float4 cv = ring4[lane];                      // slot 0, lane chunk
    float  cb = ringf[128];                       // slot 0, blank

    // ---- forward Viterbi, t in [0, ss) ----
    for (int t = 0; t < ss; ++t) {
        step(t, cb, cv.x, cv.y, cv.z, cv.w);
        issue_row(t + RING);
        CP_WAIT14();                              // rows <= t+2 resident
        const int slot = (t + 1) & (RING - 1);
        cv = ring4[slot * (ROWB / 16) + lane];
        cb = ringf[slot * GROW + 128];
    }

    // ---------------- score / start state (alpha at t = ss is in regs) ----------------
#pragma unroll
    for (int k = 0; k < 9; k++) {
        const int s = 8 * lane + k;
        if (s < LSTATES) alphaAt[s] = a[k];
    }
    __syncwarp();
    if (lane == 0) {
        const float s1 = alphaAt[pl - 1];
        const float s2 = alphaAt[pl - 2];
        start_sh = (s1 > s2) ? (pl - 1) : (pl - 2);
        out[b] = fmaxf(s1, s2);                              // score
        out[32 + MASK_ELEMS + b] = (float)(yl + 1);          // ylens + 1
    }
    __syncwarp();

    // ---------------- backtrace (lane 0, LDS chase) ----------------
    for (int t = ss + lane; t < XMAX; t += 32) states_sh[t] = 0;
    if (lane == 0) {
        int carry = start_sh;
        states_sh[ss - 1] = (short)carry;
        for (int t = ss - 2; t >= 0; --t) {
            int lidx = carry >> 3; if (lidx > 31) lidx = 31;   // state 256 -> lane31,k=8
            const uint32_t word = bp_sm[(t + 1) * 32 + lidx];
            const int kk = carry - (lidx << 3);
            carry -= (int)((word >> (2 * kk)) & 3u);
            states_sh[t] = (short)carry;
        }
    }
    __syncwarp();

    // ---------------- collapse repeats + exclusive non-blank count ----------------
    const int base_t = lane * 32;
    int prevTok = 0;
    if (base_t > 0) {
        const int sp = states_sh[base_t - 1];
        prevTok = (sp & 1) ? ys[b * YMAX + ((sp - 1) >> 1)] : blank;
    }
    int lane_sum = 0;
    {
        int pt = prevTok;
        for (int i = 0; i < 32; i++) {
            const int st = states_sh[base_t + i];
            const int tk = (st & 1) ? ys[b * YMAX + ((st - 1) >> 1)] : blank;
            const int col = (tk == pt) ? 0 : tk;
            lane_sum += (col != blank) ? 1 : 0;
            pt = tk;
        }
    }
    int offs = lane_sum;
#pragma unroll
    for (int d = 1; d < 32; d <<= 1) {
        const int v = __shfl_up_sync(0xffffffffu, offs, d);
        if (lane >= d) offs += v;
    }
    offs -= lane_sum;
    {
        int pt = prevTok, run = offs;
        for (int i = 0; i < 32; i++) {
            const int t = base_t + i;
            g_csum[b * XMAX + t] = (short)run;               // exclusive count at t
            const int st = states_sh[t];
            const int tk = (st & 1) ? ys[b * YMAX + ((st - 1) >> 1)] : blank;
            const int col = (tk == pt) ? 0 : tk;
            run += (col != blank) ? 1 : 0;
            pt = tk;
        }
    }
    if (lane == 0) g_ssv[b] = ss;
}

// ---------------- Stage 3: trigger_mask streaming store ----------------
// grid: (per_b/4/256 = 129, BSZ) -> no 64-bit div/mod in the hot path
__global__ __launch_bounds__(256)
void fanat_mask(float* __restrict__ out)
{
    const int bb   = blockIdx.y;
    const int idx4 = blockIdx.x * 256 + threadIdx.x;        // [0, 33024)
    const int rem  = idx4 * 4;                              // [0, 132096)
    const int j    = rem >> 10;                             // XMAX = 1024
    const int t0   = rem & (XMAX - 1);

    const int ss = g_ssv[bb];
    const short4 cs = *(const short4*)(g_csum + bb * XMAX + t0);
    const int cv[4] = {cs.x, cs.y, cs.z, cs.w};

    float4 v;
    float* vv = &v.x;
#pragma unroll
    for (int u = 0; u < 4; u++) {
        const int t = t0 + u;
        const bool in = (t < ss);
        const int c = cv[u];
        bool r;
        if (j < YMAX) r = in && (c == j);
        else          r = in && (c == YMAX || t == ss - 1);
        vv[u] = r ? 1.0f : 0.0f;
    }
    const size_t e = (size_t)bb * ((YMAX + 1) * XMAX) + rem;
    *(float4*)(out + 32 + e) = v;
}

extern "C" void kernel_launch(void* const* d_in, const int* in_sizes, int n_in,
                              void* d_out, int out_size)
{
    // metadata order: ctc_out(f32), src_mask(bool, unused), src_size(i32),
    //                 ys(i32), ylens(i32), blank(i32 scalar)
    const float* ctc      = (const float*)d_in[0];
    const int*   src_size = (const int*)d_in[2];
    const int*   ys       = (const int*)d_in[3];
    const int*   ylens    = (const int*)d_in[4];
    const int*   blank_p  = (n_in > 5) ? (const int*)d_in[5] : nullptr;

    {   // Stage 1: gather
        const int total = BSZ * XMAX * GROW;
        fanat_gather<<<(total + 255) / 256, 256>>>(ctc, ys, blank_p);
    }

    {   // Stage 2: forward Viterbi + backtrace + csum
        const int smem = XMAX * 32 * (int)sizeof(uint32_t) + RING * ROWB;  // 128K + 8.25K
        cudaFuncSetAttribute(fanat_forward,
                             cudaFuncAttributeMaxDynamicSharedMemorySize, smem);
        fanat_forward<<<BSZ, 32, smem>>>(src_size, ys, ylens, blank_p, (float*)d_out);
    }

    {   // Stage 3: trigger_mask
        dim3 grid((YMAX + 1) * XMAX / 4 / 256, BSZ);        // (129, 32)
        fanat_mask<<<grid, 256>>>((float*)d_out);
    }
}